// round 3
// baseline (speedup 1.0000x reference)
#include <cuda_runtime.h>
#include <math.h>

// Problem constants (fixed by reference setup_inputs)
#define BATCH 8
#define C_IN 128
#define N_SIDE 256
#define N_PIX 65536           // N_SIDE*N_SIDE
#define PSQ 64                // POOL*POOL
#define CH 128                // 2*PSQ
#define PN 1024               // PATH_NUM = N_PIX/PSQ

// ---------------- scratch (static device globals; no allocation) -------------
__device__ float g_x1[BATCH * 2 * N_PIX];       // mean/max per pixel   4 MB
__device__ float g_feat[BATCH * CH * PN];       // feat[b][c][p]        4 MB
__device__ float g_Q[BATCH * CH * PN];          // 4 MB
__device__ float g_K[BATCH * CH * PN];          // 4 MB
__device__ float g_V[BATCH * CH * PN];          // 4 MB
__device__ float g_S[BATCH * PN * PN];          // S[b][q][p] = scores[p][q]  32 MB
__device__ float g_X3[BATCH * CH * PN];         // x3c[b][c][p]         4 MB
__device__ float g_sig[BATCH * N_PIX];          // sigmoid gate         2 MB

// ---------------- kernel 1: mean & max over channels ------------------------
__global__ void meanmax_kernel(const float* __restrict__ x) {
    int t = blockIdx.x * blockDim.x + threadIdx.x;       // 8 * 16384 threads
    int b = t >> 14;
    int w = t & 16383;                                   // float4 group within pixel dim
    const float4* xp = (const float4*)x + (long)b * C_IN * (N_PIX / 4) + w;
    float4 s = make_float4(0.f, 0.f, 0.f, 0.f);
    float4 m = make_float4(-INFINITY, -INFINITY, -INFINITY, -INFINITY);
#pragma unroll 8
    for (int c = 0; c < C_IN; c++) {
        float4 v = xp[(long)c * (N_PIX / 4)];
        s.x += v.x; s.y += v.y; s.z += v.z; s.w += v.w;
        m.x = fmaxf(m.x, v.x); m.y = fmaxf(m.y, v.y);
        m.z = fmaxf(m.z, v.z); m.w = fmaxf(m.w, v.w);
    }
    const float inv = 1.0f / 128.0f;
    s.x *= inv; s.y *= inv; s.z *= inv; s.w *= inv;
    float4* o = (float4*)g_x1;
    o[(long)b * 2 * (N_PIX / 4) + w] = s;
    o[(long)b * 2 * (N_PIX / 4) + (N_PIX / 4) + w] = m;
}

// ---------------- kernel 2: hilbert gather + pool transpose -----------------
// feat[b][s*64+j][p] = x1[b][s][hil[p*64+j]]
__global__ void gather_kernel(const int* __restrict__ hil) {
    int t = blockIdx.x * blockDim.x + threadIdx.x;       // 8 * 65536
    int b = t >> 16;
    int d = t & 65535;
    int pix = hil[d];
    int p = d >> 6;
    int j = d & 63;
    float mean = g_x1[(long)b * 2 * N_PIX + pix];
    float mx   = g_x1[(long)b * 2 * N_PIX + N_PIX + pix];
    g_feat[(long)b * CH * PN + j * PN + p]        = mean;
    g_feat[(long)b * CH * PN + (64 + j) * PN + p] = mx;
}

// ---------------- generic fp32 SGEMM ----------------------------------------
// C[b] = A[b] * B[b] (+ bias per row). A: [M,K] row-major, or [K,M] if TRANSA.
// B: [K,N] row-major. Strides are per-batch element strides (0 = shared).
template <int BM, int BN, int BK, int TM, int TN, bool TRANSA, bool BIAS>
__global__ void sgemm_kernel(const float* __restrict__ A,
                             const float* __restrict__ B,
                             const float* __restrict__ bias,
                             float* __restrict__ C,
                             int M, int N, int K,
                             long sA, long sB, long sC) {
    constexpr int THREADS = (BM / TM) * (BN / TN);
    __shared__ float As[BK][BM];
    __shared__ float Bs[BK][BN];

    const int bz = blockIdx.z;
    A += bz * sA; B += bz * sB; C += bz * sC;

    const int tid = threadIdx.x;
    const int tx = tid % (BN / TN);
    const int ty = tid / (BN / TN);
    const int row0 = blockIdx.y * BM + ty * TM;
    const int col0 = blockIdx.x * BN + tx * TN;

    float acc[TM][TN];
#pragma unroll
    for (int i = 0; i < TM; i++)
#pragma unroll
        for (int j = 0; j < TN; j++) acc[i][j] = 0.f;

    for (int k0 = 0; k0 < K; k0 += BK) {
        if (TRANSA) {
            // A stored [K][M]
#pragma unroll
            for (int idx = tid; idx < BK * BM / 4; idx += THREADS) {
                int k = idx / (BM / 4);
                int m4 = idx % (BM / 4);
                float4 v = *(const float4*)&A[(long)(k0 + k) * M + blockIdx.y * BM + m4 * 4];
                *(float4*)&As[k][m4 * 4] = v;
            }
        } else {
            // A stored [M][K]
#pragma unroll
            for (int idx = tid; idx < BK * BM / 4; idx += THREADS) {
                int m = idx / (BK / 4);
                int kq = idx % (BK / 4);
                float4 v = *(const float4*)&A[(long)(blockIdx.y * BM + m) * K + k0 + kq * 4];
                As[kq * 4 + 0][m] = v.x;
                As[kq * 4 + 1][m] = v.y;
                As[kq * 4 + 2][m] = v.z;
                As[kq * 4 + 3][m] = v.w;
            }
        }
#pragma unroll
        for (int idx = tid; idx < BK * BN / 4; idx += THREADS) {
            int k = idx / (BN / 4);
            int n4 = idx % (BN / 4);
            float4 v = *(const float4*)&B[(long)(k0 + k) * N + blockIdx.x * BN + n4 * 4];
            *(float4*)&Bs[k][n4 * 4] = v;
        }
        __syncthreads();

#pragma unroll
        for (int k = 0; k < BK; k++) {
            float a[TM], bb[TN];
#pragma unroll
            for (int i = 0; i < TM; i++) a[i] = As[k][ty * TM + i];
#pragma unroll
            for (int j = 0; j < TN; j++) bb[j] = Bs[k][tx * TN + j];
#pragma unroll
            for (int i = 0; i < TM; i++)
#pragma unroll
                for (int j = 0; j < TN; j++) acc[i][j] += a[i] * bb[j];
        }
        __syncthreads();
    }

#pragma unroll
    for (int i = 0; i < TM; i++) {
        float bi = BIAS ? bias[row0 + i] : 0.f;
#pragma unroll
        for (int j = 0; j < TN; j += 4) {
            float4 v;
            v.x = acc[i][j + 0] + bi;
            v.y = acc[i][j + 1] + bi;
            v.z = acc[i][j + 2] + bi;
            v.w = acc[i][j + 3] + bi;
            *(float4*)&C[(long)(row0 + i) * N + col0 + j] = v;
        }
    }
}

// ---------------- kernel: row softmax over contiguous dim (length 1024) -----
// S[b][q][p] rows: softmax over p (matches reference softmax over axis=1 of scores[p][q])
__global__ void softmax_kernel() {
    float* r = g_S + (long)blockIdx.x * PN;
    int t = threadIdx.x;                      // 256 threads, 1 float4 each
    float4 v = ((float4*)r)[t];

    __shared__ float redmax[8];
    __shared__ float redsum[8];

    float m = fmaxf(fmaxf(v.x, v.y), fmaxf(v.z, v.w));
#pragma unroll
    for (int o = 16; o > 0; o >>= 1) m = fmaxf(m, __shfl_xor_sync(0xffffffffu, m, o));
    if ((t & 31) == 0) redmax[t >> 5] = m;
    __syncthreads();
    if (t < 32) {
        float x = (t < 8) ? redmax[t] : -INFINITY;
#pragma unroll
        for (int o = 4; o > 0; o >>= 1) x = fmaxf(x, __shfl_xor_sync(0xffffffffu, x, o));
        if (t == 0) redmax[0] = x;
    }
    __syncthreads();
    float bm = redmax[0];

    float e0 = expf(v.x - bm), e1 = expf(v.y - bm), e2 = expf(v.z - bm), e3 = expf(v.w - bm);
    float s = e0 + e1 + e2 + e3;
#pragma unroll
    for (int o = 16; o > 0; o >>= 1) s += __shfl_xor_sync(0xffffffffu, s, o);
    if ((t & 31) == 0) redsum[t >> 5] = s;
    __syncthreads();
    if (t < 32) {
        float x = (t < 8) ? redsum[t] : 0.f;
#pragma unroll
        for (int o = 4; o > 0; o >>= 1) x += __shfl_xor_sync(0xffffffffu, x, o);
        if (t == 0) redsum[0] = x;
    }
    __syncthreads();
    float inv = 1.0f / redsum[0];

    v.x = e0 * inv; v.y = e1 * inv; v.z = e2 * inv; v.w = e3 * inv;
    ((float4*)r)[t] = v;
}

// ---------------- kernel: inverse hilbert + sigmoid gate --------------------
__global__ void sig_kernel(const int* __restrict__ rehil,
                           const float* __restrict__ Wpre,
                           const float* __restrict__ bpre) {
    int t = blockIdx.x * blockDim.x + threadIdx.x;       // 8 * 65536
    int b = t >> 16;
    int pix = t & 65535;
    int d = rehil[pix];
    int p = d >> 6;
    int j = d & 63;
    float r0 = g_X3[(long)b * CH * PN + j * PN + p];
    float r1 = g_X3[(long)b * CH * PN + (64 + j) * PN + p];
    float att = Wpre[0] * r0 + Wpre[1] * r1 + bpre[0];
    g_sig[t] = 1.0f / (1.0f + expf(-att));
}

// ---------------- kernel: final elementwise out = sig * x -------------------
__global__ void final_kernel(const float* __restrict__ x, float* __restrict__ out) {
    long i = blockIdx.x * (long)blockDim.x + threadIdx.x; // 16,777,216 float4
    int pixw = (int)(i & 16383);
    long bc = i >> 14;
    int b = (int)(bc >> 7);
    float4 s = ((const float4*)g_sig)[(long)b * (N_PIX / 4) + pixw];
    float4 v = ((const float4*)x)[i];
    v.x *= s.x; v.y *= s.y; v.z *= s.z; v.w *= s.w;
    ((float4*)out)[i] = v;
}

// ---------------- launch ------------------------------------------------------
extern "C" void kernel_launch(void* const* d_in, const int* in_sizes, int n_in,
                              void* d_out, int out_size) {
    const float* x    = (const float*)d_in[0];
    const float* Wq   = (const float*)d_in[1];
    const float* bq   = (const float*)d_in[2];
    const float* Wk   = (const float*)d_in[3];
    const float* bk   = (const float*)d_in[4];
    const float* Wv   = (const float*)d_in[5];
    const float* bv   = (const float*)d_in[6];
    const float* Wpre = (const float*)d_in[7];
    const float* bpre = (const float*)d_in[8];
    const int*   hil  = (const int*)d_in[9];
    const int*   rehil= (const int*)d_in[10];
    float* out = (float*)d_out;

    float *pX1, *pFeat, *pQ, *pK, *pV, *pS, *pX3;
    cudaGetSymbolAddress((void**)&pX1, g_x1);
    cudaGetSymbolAddress((void**)&pFeat, g_feat);
    cudaGetSymbolAddress((void**)&pQ, g_Q);
    cudaGetSymbolAddress((void**)&pK, g_K);
    cudaGetSymbolAddress((void**)&pV, g_V);
    cudaGetSymbolAddress((void**)&pS, g_S);
    cudaGetSymbolAddress((void**)&pX3, g_X3);

    // 1) mean/max over channels
    meanmax_kernel<<<(BATCH * (N_PIX / 4)) / 256, 256>>>(x);

    // 2) hilbert gather -> feat
    gather_kernel<<<(BATCH * N_PIX) / 256, 256>>>(hil);

    // 3) Q, K, V = W @ feat + b   (M=128, N=1024, K=128)
    {
        dim3 grid(PN / 128, CH / 128, BATCH);
        sgemm_kernel<128, 128, 8, 8, 8, false, true><<<grid, 256>>>(
            Wq, pFeat, bq, pQ, CH, PN, CH, 0, (long)CH * PN, (long)CH * PN);
        sgemm_kernel<128, 128, 8, 8, 8, false, true><<<grid, 256>>>(
            Wk, pFeat, bk, pK, CH, PN, CH, 0, (long)CH * PN, (long)CH * PN);
        sgemm_kernel<128, 128, 8, 8, 8, false, true><<<grid, 256>>>(
            Wv, pFeat, bv, pV, CH, PN, CH, 0, (long)CH * PN, (long)CH * PN);
    }

    // 4) S[b][q][p] = sum_c K[c][q] * Q[c][p]   (M=1024(q), N=1024(p), K=128, A=K transposed-access)
    {
        dim3 grid(PN / 128, PN / 128, BATCH);
        sgemm_kernel<128, 128, 8, 8, 8, true, false><<<grid, 256>>>(
            pK, pQ, nullptr, pS, PN, PN, CH,
            (long)CH * PN, (long)CH * PN, (long)PN * PN);
    }

    // 5) softmax over p (contiguous dim of S rows)
    softmax_kernel<<<BATCH * PN, 256>>>();

    // 6) x3c[c][p] = sum_q V[c][q] * A[q][p]    (M=128, N=1024, K=1024)
    {
        dim3 grid(PN / 64, CH / 128, BATCH);
        sgemm_kernel<128, 64, 8, 8, 4, false, false><<<grid, 256>>>(
            pV, pS, nullptr, pX3, CH, PN, PN,
            (long)CH * PN, (long)PN * PN, (long)CH * PN);
    }

    // 7) inverse hilbert + pre-conv + sigmoid gate
    sig_kernel<<<(BATCH * N_PIX) / 256, 256>>>(rehil, Wpre, bpre);

    // 8) out = sigmoid(att) * x
    final_kernel<<<(BATCH * C_IN * (N_PIX / 4)) / 256, 256>>>(x, out);
}

// round 4
// speedup vs baseline: 1.3065x; 1.3065x over previous
#include <cuda_runtime.h>
#include <math.h>

// Problem constants (fixed by reference setup_inputs)
#define BATCH 8
#define C_IN 128
#define N_SIDE 256
#define N_PIX 65536           // N_SIDE*N_SIDE
#define PSQ 64                // POOL*POOL
#define CH 128                // 2*PSQ
#define PN 1024               // PATH_NUM = N_PIX/PSQ

// ---------------- scratch (static device globals; no allocation) -------------
__device__ float g_x1[BATCH * 2 * N_PIX];        // mean/max per pixel
__device__ float g_feat[BATCH * CH * PN];        // feat[b][c][p]
__device__ float g_Q[BATCH * CH * PN];
__device__ float g_K[BATCH * CH * PN];
__device__ float g_V[BATCH * CH * PN];
__device__ float g_S[BATCH * PN * PN];           // S[b][q][p] = scores[p][q]
__device__ float g_X3[2 * BATCH * CH * PN];      // split-K partials
__device__ float g_sig[BATCH * N_PIX];

// ---------------- kernel 1: mean & max over channels ------------------------
__global__ void meanmax_kernel(const float* __restrict__ x) {
    int t = blockIdx.x * blockDim.x + threadIdx.x;
    int b = t >> 14;
    int w = t & 16383;
    const float4* xp = (const float4*)x + (long)b * C_IN * (N_PIX / 4) + w;
    float4 s = make_float4(0.f, 0.f, 0.f, 0.f);
    float4 m = make_float4(-INFINITY, -INFINITY, -INFINITY, -INFINITY);
#pragma unroll 8
    for (int c = 0; c < C_IN; c++) {
        float4 v = xp[(long)c * (N_PIX / 4)];
        s.x += v.x; s.y += v.y; s.z += v.z; s.w += v.w;
        m.x = fmaxf(m.x, v.x); m.y = fmaxf(m.y, v.y);
        m.z = fmaxf(m.z, v.z); m.w = fmaxf(m.w, v.w);
    }
    const float inv = 1.0f / 128.0f;
    s.x *= inv; s.y *= inv; s.z *= inv; s.w *= inv;
    float4* o = (float4*)g_x1;
    o[(long)b * 2 * (N_PIX / 4) + w] = s;
    o[(long)b * 2 * (N_PIX / 4) + (N_PIX / 4) + w] = m;
}

// ---------------- kernel 2: hilbert gather + pool transpose -----------------
__global__ void gather_kernel(const int* __restrict__ hil) {
    int t = blockIdx.x * blockDim.x + threadIdx.x;
    int b = t >> 16;
    int d = t & 65535;
    int pix = hil[d];
    int p = d >> 6;
    int j = d & 63;
    float mean = g_x1[(long)b * 2 * N_PIX + pix];
    float mx   = g_x1[(long)b * 2 * N_PIX + N_PIX + pix];
    g_feat[(long)b * CH * PN + j * PN + p]        = mean;
    g_feat[(long)b * CH * PN + (64 + j) * PN + p] = mx;
}

// ---------------- shared SGEMM body with global->reg prefetch pipeline ------
// C[row][col] = sum_k A*B (+bias). A: [M,K] row-major, or [K,M] if TRANSA.
// B: [K,N] row-major. K range [k_begin, k_end).
template <int BM, int BN, int BK, int TM, int TN, bool TRANSA, bool BIAS>
__device__ __forceinline__ void gemm_body(
    const float* __restrict__ A, const float* __restrict__ B,
    const float* __restrict__ bias, float* __restrict__ C,
    int M, int N, int K, int bx, int by, int k_begin, int k_end)
{
    constexpr int THREADS = (BM / TM) * (BN / TN);
    constexpr int A_V = BK * BM / 4 / THREADS;   // float4 loads/thread for A
    constexpr int B_V = BK * BN / 4 / THREADS;
    constexpr int BMP = BM + 4;                  // pad: fewer store conflicts

    __shared__ float As[BK][BMP];
    __shared__ float Bs[BK][BN];

    const int tid = threadIdx.x;
    const int tx = tid % (BN / TN);
    const int ty = tid / (BN / TN);

    float4 ar[A_V], br[B_V];

    auto load_tile = [&](int k0) {
#pragma unroll
        for (int u = 0; u < A_V; u++) {
            int idx = tid + u * THREADS;
            if (TRANSA) {
                int k = idx / (BM / 4);
                int m4 = idx % (BM / 4);
                ar[u] = *(const float4*)&A[(long)(k0 + k) * M + by * BM + m4 * 4];
            } else {
                int m = idx / (BK / 4);
                int kq = idx % (BK / 4);
                ar[u] = *(const float4*)&A[(long)(by * BM + m) * K + k0 + kq * 4];
            }
        }
#pragma unroll
        for (int u = 0; u < B_V; u++) {
            int idx = tid + u * THREADS;
            int k = idx / (BN / 4);
            int n4 = idx % (BN / 4);
            br[u] = *(const float4*)&B[(long)(k0 + k) * N + bx * BN + n4 * 4];
        }
    };
    auto store_tile = [&]() {
#pragma unroll
        for (int u = 0; u < A_V; u++) {
            int idx = tid + u * THREADS;
            if (TRANSA) {
                int k = idx / (BM / 4);
                int m4 = idx % (BM / 4);
                *(float4*)&As[k][m4 * 4] = ar[u];
            } else {
                int m = idx / (BK / 4);
                int kq = idx % (BK / 4);
                As[kq * 4 + 0][m] = ar[u].x;
                As[kq * 4 + 1][m] = ar[u].y;
                As[kq * 4 + 2][m] = ar[u].z;
                As[kq * 4 + 3][m] = ar[u].w;
            }
        }
#pragma unroll
        for (int u = 0; u < B_V; u++) {
            int idx = tid + u * THREADS;
            int k = idx / (BN / 4);
            int n4 = idx % (BN / 4);
            *(float4*)&Bs[k][n4 * 4] = br[u];
        }
    };

    float acc[TM][TN];
#pragma unroll
    for (int i = 0; i < TM; i++)
#pragma unroll
        for (int j = 0; j < TN; j++) acc[i][j] = 0.f;

    load_tile(k_begin);
    for (int k0 = k_begin; k0 < k_end; k0 += BK) {
        store_tile();
        __syncthreads();
        if (k0 + BK < k_end) load_tile(k0 + BK);

#pragma unroll
        for (int k = 0; k < BK; k++) {
            float a[TM], bb[TN];
#pragma unroll
            for (int i = 0; i < TM; i += 4)
                *(float4*)&a[i] = *(const float4*)&As[k][ty * TM + i];
#pragma unroll
            for (int j = 0; j < TN; j += 4)
                *(float4*)&bb[j] = *(const float4*)&Bs[k][tx * TN + j];
#pragma unroll
            for (int i = 0; i < TM; i++)
#pragma unroll
                for (int j = 0; j < TN; j++) acc[i][j] += a[i] * bb[j];
        }
        __syncthreads();
    }

    const int row0 = by * BM + ty * TM;
    const int col0 = bx * BN + tx * TN;
#pragma unroll
    for (int i = 0; i < TM; i++) {
        float bi = BIAS ? bias[row0 + i] : 0.f;
#pragma unroll
        for (int j = 0; j < TN; j += 4) {
            float4 v;
            v.x = acc[i][j + 0] + bi;
            v.y = acc[i][j + 1] + bi;
            v.z = acc[i][j + 2] + bi;
            v.w = acc[i][j + 3] + bi;
            *(float4*)&C[(long)(row0 + i) * N + col0 + j] = v;
        }
    }
}

// ---------------- fused QKV: blockIdx.y selects W/bias/output ---------------
__global__ __launch_bounds__(256) void qkv_kernel(
    const float* __restrict__ Wq, const float* __restrict__ Wk, const float* __restrict__ Wv,
    const float* __restrict__ bq, const float* __restrict__ bk, const float* __restrict__ bv,
    const float* __restrict__ feat, float* __restrict__ Q, float* __restrict__ K,
    float* __restrict__ V)
{
    int b = blockIdx.z;
    const float* W; const float* bi; float* O;
    if (blockIdx.y == 0)      { W = Wq; bi = bq; O = Q; }
    else if (blockIdx.y == 1) { W = Wk; bi = bk; O = K; }
    else                      { W = Wv; bi = bv; O = V; }
    gemm_body<128, 128, 16, 8, 8, false, true>(
        W, feat + (long)b * CH * PN, bi, O + (long)b * CH * PN,
        CH, PN, CH, blockIdx.x, 0, 0, CH);
}

// ---------------- scores: S[b][q][p] = sum_c K[c][q] * Q[c][p] ---------------
__global__ __launch_bounds__(256) void scores_kernel(
    const float* __restrict__ Kk, const float* __restrict__ Qq, float* __restrict__ S)
{
    int b = blockIdx.z;
    gemm_body<128, 128, 16, 8, 8, true, false>(
        Kk + (long)b * CH * PN, Qq + (long)b * CH * PN, nullptr, S + (long)b * PN * PN,
        PN, PN, CH, blockIdx.x, blockIdx.y, 0, CH);
}

// ---------------- x3c split-K=2: partials into g_X3[ks] ---------------------
__global__ __launch_bounds__(256) void x3_kernel(
    const float* __restrict__ V, const float* __restrict__ S, float* __restrict__ X3)
{
    int b = blockIdx.z;
    int bx = blockIdx.x >> 1;
    int ks = blockIdx.x & 1;
    gemm_body<128, 64, 16, 8, 4, false, false>(
        V + (long)b * CH * PN, S + (long)b * PN * PN, nullptr,
        X3 + (long)ks * BATCH * CH * PN + (long)b * CH * PN,
        CH, PN, PN, bx, 0, ks * (PN / 2), ks * (PN / 2) + (PN / 2));
}

// ---------------- row softmax over contiguous dim (length 1024) -------------
__global__ void softmax_kernel() {
    float* r = g_S + (long)blockIdx.x * PN;
    int t = threadIdx.x;
    float4 v = ((float4*)r)[t];

    __shared__ float redmax[8];
    __shared__ float redsum[8];

    float m = fmaxf(fmaxf(v.x, v.y), fmaxf(v.z, v.w));
#pragma unroll
    for (int o = 16; o > 0; o >>= 1) m = fmaxf(m, __shfl_xor_sync(0xffffffffu, m, o));
    if ((t & 31) == 0) redmax[t >> 5] = m;
    __syncthreads();
    if (t < 32) {
        float x = (t < 8) ? redmax[t] : -INFINITY;
#pragma unroll
        for (int o = 4; o > 0; o >>= 1) x = fmaxf(x, __shfl_xor_sync(0xffffffffu, x, o));
        if (t == 0) redmax[0] = x;
    }
    __syncthreads();
    float bm = redmax[0];

    float e0 = expf(v.x - bm), e1 = expf(v.y - bm), e2 = expf(v.z - bm), e3 = expf(v.w - bm);
    float s = e0 + e1 + e2 + e3;
#pragma unroll
    for (int o = 16; o > 0; o >>= 1) s += __shfl_xor_sync(0xffffffffu, s, o);
    if ((t & 31) == 0) redsum[t >> 5] = s;
    __syncthreads();
    if (t < 32) {
        float x = (t < 8) ? redsum[t] : 0.f;
#pragma unroll
        for (int o = 4; o > 0; o >>= 1) x += __shfl_xor_sync(0xffffffffu, x, o);
        if (t == 0) redsum[0] = x;
    }
    __syncthreads();
    float inv = 1.0f / redsum[0];

    v.x = e0 * inv; v.y = e1 * inv; v.z = e2 * inv; v.w = e3 * inv;
    ((float4*)r)[t] = v;
}

// ---------------- inverse hilbert + combine split-K + sigmoid gate ----------
__global__ void sig_kernel(const int* __restrict__ rehil,
                           const float* __restrict__ Wpre,
                           const float* __restrict__ bpre) {
    int t = blockIdx.x * blockDim.x + threadIdx.x;
    int b = t >> 16;
    int pix = t & 65535;
    int d = rehil[pix];
    int p = d >> 6;
    int j = d & 63;
    const long half = (long)BATCH * CH * PN;
    long base = (long)b * CH * PN;
    float r0 = g_X3[base + j * PN + p]        + g_X3[half + base + j * PN + p];
    float r1 = g_X3[base + (64 + j) * PN + p] + g_X3[half + base + (64 + j) * PN + p];
    float att = Wpre[0] * r0 + Wpre[1] * r1 + bpre[0];
    g_sig[t] = 1.0f / (1.0f + expf(-att));
}

// ---------------- final elementwise out = sig * x ----------------------------
__global__ void final_kernel(const float* __restrict__ x, float* __restrict__ out) {
    long i = blockIdx.x * (long)blockDim.x + threadIdx.x;
    int pixw = (int)(i & 16383);
    long bc = i >> 14;
    int b = (int)(bc >> 7);
    float4 s = ((const float4*)g_sig)[(long)b * (N_PIX / 4) + pixw];
    float4 v = ((const float4*)x)[i];
    v.x *= s.x; v.y *= s.y; v.z *= s.z; v.w *= s.w;
    ((float4*)out)[i] = v;
}

// ---------------- launch ------------------------------------------------------
extern "C" void kernel_launch(void* const* d_in, const int* in_sizes, int n_in,
                              void* d_out, int out_size) {
    const float* x    = (const float*)d_in[0];
    const float* Wq   = (const float*)d_in[1];
    const float* bq   = (const float*)d_in[2];
    const float* Wk   = (const float*)d_in[3];
    const float* bk   = (const float*)d_in[4];
    const float* Wv   = (const float*)d_in[5];
    const float* bv   = (const float*)d_in[6];
    const float* Wpre = (const float*)d_in[7];
    const float* bpre = (const float*)d_in[8];
    const int*   hil  = (const int*)d_in[9];
    const int*   rehil= (const int*)d_in[10];
    float* out = (float*)d_out;

    float *pFeat, *pQ, *pK, *pV, *pS, *pX3;
    cudaGetSymbolAddress((void**)&pFeat, g_feat);
    cudaGetSymbolAddress((void**)&pQ, g_Q);
    cudaGetSymbolAddress((void**)&pK, g_K);
    cudaGetSymbolAddress((void**)&pV, g_V);
    cudaGetSymbolAddress((void**)&pS, g_S);
    cudaGetSymbolAddress((void**)&pX3, g_X3);

    // 1) mean/max over channels
    meanmax_kernel<<<(BATCH * (N_PIX / 4)) / 256, 256>>>(x);

    // 2) hilbert gather -> feat
    gather_kernel<<<(BATCH * N_PIX) / 256, 256>>>(hil);

    // 3) fused Q,K,V = W @ feat + b   (192 blocks)
    {
        dim3 grid(PN / 128, 3, BATCH);
        qkv_kernel<<<grid, 256>>>(Wq, Wk, Wv, bq, bk, bv, pFeat, pQ, pK, pV);
    }

    // 4) scores (512 blocks)
    {
        dim3 grid(PN / 128, PN / 128, BATCH);
        scores_kernel<<<grid, 256>>>(pK, pQ, pS);
    }

    // 5) softmax over p
    softmax_kernel<<<BATCH * PN, 256>>>();

    // 6) x3c split-K=2 (256 blocks)
    {
        dim3 grid((PN / 64) * 2, 1, BATCH);
        x3_kernel<<<grid, 256>>>(pV, pS, pX3);
    }

    // 7) inverse hilbert + split-K combine + sigmoid gate
    sig_kernel<<<(BATCH * N_PIX) / 256, 256>>>(rehil, Wpre, bpre);

    // 8) out = sigmoid(att) * x
    final_kernel<<<(BATCH * C_IN * (N_PIX / 4)) / 256, 256>>>(x, out);
}

// round 6
// speedup vs baseline: 1.6326x; 1.2496x over previous
#include <cuda_runtime.h>
#include <cuda_bf16.h>
#include <math.h>
#include <stdint.h>

#define BATCH 8
#define C_IN 128
#define N_PIX 65536
#define CH 128
#define PN 1024

typedef __nv_bfloat16 bf16;

// ---------------- scratch (static device globals; no allocation) ------------
__device__ float g_x1[BATCH * 2 * N_PIX];
__device__ float g_feat[BATCH * CH * PN];
__device__ bf16  g_Qs[BATCH * PN * 256];      // Q^T: [b][p][hi(128)|lo(128)]
__device__ bf16  g_Ks[BATCH * PN * 256];      // K^T: [b][q][hi(128)|lo(128)]
__device__ bf16  g_Vhi[BATCH * CH * PN];      // V hi: [b][c][q]
__device__ bf16  g_Vlo[BATCH * CH * PN];
__device__ float g_S[BATCH * PN * PN];        // scores [b][q][p]  32 MB
__device__ float g_smax[BATCH * PN];
__device__ float g_sinv[BATCH * PN];
__device__ bf16  g_aThi[BATCH * PN * PN];     // att^T hi: [b][p][q]
__device__ bf16  g_aTlo[BATCH * PN * PN];
__device__ float g_X3[4 * BATCH * CH * PN];   // split-K=4 partials
__device__ float g_sig[BATCH * N_PIX];

// ---------------- helpers -----------------------------------------------------
__device__ __forceinline__ uint32_t s2u(const void* p) {
    uint32_t a;
    asm("{ .reg .u64 t; cvta.to.shared.u64 t, %1; cvt.u32.u64 %0, t; }" : "=r"(a) : "l"(p));
    return a;
}
#define SW128(off) ((off) ^ (((off) >> 3) & 0x70))

__device__ __forceinline__ void cp16(uint32_t dst, const void* src) {
    asm volatile("cp.async.cg.shared.global [%0], [%1], 16;" :: "r"(dst), "l"(src));
}
#define LDMX4(r0, r1, r2, r3, addr)                                            \
    asm volatile("ldmatrix.sync.aligned.m8n8.x4.shared.b16 {%0,%1,%2,%3}, [%4];" \
                 : "=r"(r0), "=r"(r1), "=r"(r2), "=r"(r3) : "r"(addr))
#define MMA16816(d, a, b)                                                      \
    asm volatile("mma.sync.aligned.m16n8k16.row.col.f32.bf16.bf16.f32 "        \
                 "{%0,%1,%2,%3},{%4,%5,%6,%7},{%8,%9},{%0,%1,%2,%3};"          \
                 : "+f"((d)[0]), "+f"((d)[1]), "+f"((d)[2]), "+f"((d)[3])      \
                 : "r"((a)[0]), "r"((a)[1]), "r"((a)[2]), "r"((a)[3]),         \
                   "r"((b)[0]), "r"((b)[1]))

// ---------------- 128x128 bf16 hi/lo GEMM body via mma.sync ------------------
// D[m][n] = sum over 3 passes, sum_{k=kbeg}^{kend} A[m][k]*B[n][k], fp32 accum.
// A: 128 rows (m), k-contiguous, row stride sA (elems). B: 128 rows (n), stride sB.
// Requires 64 KB dynamic smem. 256 threads.
__device__ __forceinline__ void mma_gemm3(
    const bf16* A0, const bf16* B0,
    const bf16* A1, const bf16* B1,
    const bf16* A2, const bf16* B2,
    long sA, long sB, int kbeg, int kend,
    float* C, int ldC)
{
    extern __shared__ char smem[];
    const uint32_t sb = s2u(smem);
    const int tid = threadIdx.x, lane = tid & 31, wid = tid >> 5;
    const int wm = wid & 3;                   // 4 warps along m (32 rows each)
    const int wn = wid >> 2;                  // 2 warps along n (64 cols each)

    const int nk = (kend - kbeg) >> 6;        // 64-wide k chunks per pass
    const int total = 3 * nk;

    float acc[2][8][4];
#pragma unroll
    for (int i = 0; i < 2; i++)
#pragma unroll
        for (int j = 0; j < 8; j++)
#pragma unroll
            for (int v = 0; v < 4; v++) acc[i][j][v] = 0.f;

    auto issue = [&](int chunk) {
        int pass = chunk / nk, kk = chunk - pass * nk;
        const bf16* A = (pass == 0) ? A0 : (pass == 1) ? A1 : A2;
        const bf16* B = (pass == 0) ? B0 : (pass == 1) ? B1 : B2;
        long k0 = kbeg + kk * 64;
        uint32_t aoff = (chunk & 1) * 16384u;
        uint32_t boff = 32768u + (chunk & 1) * 16384u;
#pragma unroll
        for (int u = 0; u < 4; u++) {
            int seg = tid + u * 256;          // 0..1023
            int r = seg >> 3, s = (seg & 7) * 16;
            cp16(sb + aoff + SW128(r * 128 + s), (const char*)(A + (long)r * sA + k0) + s);
        }
#pragma unroll
        for (int u = 0; u < 4; u++) {
            int seg = tid + u * 256;
            int r = seg >> 3, s = (seg & 7) * 16;
            cp16(sb + boff + SW128(r * 128 + s), (const char*)(B + (long)r * sB + k0) + s);
        }
        asm volatile("cp.async.commit_group;" ::: "memory");
    };

    issue(0);
    for (int c = 0; c < total; c++) {
        if (c + 1 < total) {
            issue(c + 1);
            asm volatile("cp.async.wait_group 1;" ::: "memory");
        } else {
            asm volatile("cp.async.wait_group 0;" ::: "memory");
        }
        __syncthreads();

        const uint32_t abase = sb + (c & 1) * 16384u;
        const uint32_t bbase = sb + 32768u + (c & 1) * 16384u;
#pragma unroll
        for (int ks = 0; ks < 4; ks++) {
            uint32_t a[2][4], bf[8][2];
#pragma unroll
            for (int mf = 0; mf < 2; mf++) {
                int r = wm * 32 + mf * 16 + (lane & 15);
                int kb = ks * 32 + ((lane >> 4) << 4);
                LDMX4(a[mf][0], a[mf][1], a[mf][2], a[mf][3],
                      abase + SW128(r * 128 + kb));
            }
#pragma unroll
            for (int ng = 0; ng < 4; ng++) {
                int r = wn * 64 + ng * 16 + (lane & 7) + ((lane >> 4) << 3);
                int kb = ks * 32 + (((lane >> 3) & 1) << 4);
                LDMX4(bf[ng * 2][0], bf[ng * 2][1], bf[ng * 2 + 1][0], bf[ng * 2 + 1][1],
                      bbase + SW128(r * 128 + kb));
            }
#pragma unroll
            for (int mf = 0; mf < 2; mf++)
#pragma unroll
                for (int nf = 0; nf < 8; nf++)
                    MMA16816(acc[mf][nf], a[mf], bf[nf]);
        }
        __syncthreads();
    }

    // epilogue: write fp32 accumulators to C
    const int g = lane >> 2, t = lane & 3;
#pragma unroll
    for (int mf = 0; mf < 2; mf++) {
        int row = wm * 32 + mf * 16 + g;
#pragma unroll
        for (int nf = 0; nf < 8; nf++) {
            int col = wn * 64 + (nf >> 1) * 16 + (nf & 1) * 8 + 2 * t;
            *(float2*)&C[(long)row * ldC + col] =
                make_float2(acc[mf][nf][0], acc[mf][nf][1]);
            *(float2*)&C[(long)(row + 8) * ldC + col] =
                make_float2(acc[mf][nf][2], acc[mf][nf][3]);
        }
    }
}

// ---------------- kernel 1: mean & max over channels ------------------------
__global__ void meanmax_kernel(const float* __restrict__ x) {
    int t = blockIdx.x * blockDim.x + threadIdx.x;
    int b = t >> 14;
    int w = t & 16383;
    const float4* xp = (const float4*)x + (long)b * C_IN * (N_PIX / 4) + w;
    float4 s = make_float4(0.f, 0.f, 0.f, 0.f);
    float4 m = make_float4(-INFINITY, -INFINITY, -INFINITY, -INFINITY);
#pragma unroll 8
    for (int c = 0; c < C_IN; c++) {
        float4 v = xp[(long)c * (N_PIX / 4)];
        s.x += v.x; s.y += v.y; s.z += v.z; s.w += v.w;
        m.x = fmaxf(m.x, v.x); m.y = fmaxf(m.y, v.y);
        m.z = fmaxf(m.z, v.z); m.w = fmaxf(m.w, v.w);
    }
    const float inv = 1.0f / 128.0f;
    s.x *= inv; s.y *= inv; s.z *= inv; s.w *= inv;
    float4* o = (float4*)g_x1;
    o[(long)b * 2 * (N_PIX / 4) + w] = s;
    o[(long)b * 2 * (N_PIX / 4) + (N_PIX / 4) + w] = m;
}

// ---------------- kernel 2: hilbert gather + pool transpose -----------------
__global__ void gather_kernel(const int* __restrict__ hil) {
    int t = blockIdx.x * blockDim.x + threadIdx.x;
    int b = t >> 16;
    int d = t & 65535;
    int pix = hil[d];
    int p = d >> 6;
    int j = d & 63;
    float mean = g_x1[(long)b * 2 * N_PIX + pix];
    float mx   = g_x1[(long)b * 2 * N_PIX + N_PIX + pix];
    g_feat[(long)b * CH * PN + j * PN + p]        = mean;
    g_feat[(long)b * CH * PN + (64 + j) * PN + p] = mx;
}

// ---------------- QKV SIMT GEMM with bf16-split epilogues -------------------
__global__ __launch_bounds__(256) void qkv_kernel(
    const float* __restrict__ Wq, const float* __restrict__ Wk, const float* __restrict__ Wv,
    const float* __restrict__ bq, const float* __restrict__ bk, const float* __restrict__ bv)
{
    __shared__ float As[16][132];
    __shared__ float Bs[16][128];

    int b = blockIdx.z;
    int p0 = blockIdx.x * 128;
    int y = blockIdx.y;
    const float* W    = (y == 0) ? Wq : (y == 1) ? Wk : Wv;
    const float* bias = (y == 0) ? bq : (y == 1) ? bk : bv;
    const float* B = g_feat + (long)b * CH * PN;

    int tid = threadIdx.x;
    int tx = tid & 15;
    int ty = tid >> 4;

    float acc[8][8];
#pragma unroll
    for (int i = 0; i < 8; i++)
#pragma unroll
        for (int j = 0; j < 8; j++) acc[i][j] = 0.f;

    for (int k0 = 0; k0 < CH; k0 += 16) {
#pragma unroll
        for (int u = 0; u < 2; u++) {
            int idx = tid + u * 256;
            int m = idx >> 2, kq = (idx & 3) * 4;
            float4 v = *(const float4*)&W[(long)m * CH + k0 + kq];
            As[kq + 0][m] = v.x; As[kq + 1][m] = v.y;
            As[kq + 2][m] = v.z; As[kq + 3][m] = v.w;
        }
#pragma unroll
        for (int u = 0; u < 2; u++) {
            int idx = tid + u * 256;
            int k = idx >> 5, n4 = (idx & 31) * 4;
            *(float4*)&Bs[k][n4] = *(const float4*)&B[(long)(k0 + k) * PN + p0 + n4];
        }
        __syncthreads();
#pragma unroll
        for (int k = 0; k < 16; k++) {
            float a[8], bb[8];
#pragma unroll
            for (int i = 0; i < 8; i++) a[i] = As[k][ty * 8 + i];
#pragma unroll
            for (int j = 0; j < 8; j++) bb[j] = Bs[k][tx * 8 + j];
#pragma unroll
            for (int i = 0; i < 8; i++)
#pragma unroll
                for (int j = 0; j < 8; j++) acc[i][j] += a[i] * bb[j];
        }
        __syncthreads();
    }

    int o0 = ty * 8;
    int pl0 = p0 + tx * 8;
    float bi[8];
#pragma unroll
    for (int i = 0; i < 8; i++) bi[i] = bias[o0 + i];

    if (y == 2) {
        bf16* H = g_Vhi + (long)b * CH * PN;
        bf16* L = g_Vlo + (long)b * CH * PN;
#pragma unroll
        for (int i = 0; i < 8; i++) {
            uint4 uh, ul;
            bf16* hp = (bf16*)&uh; bf16* lp = (bf16*)&ul;
#pragma unroll
            for (int j = 0; j < 8; j++) {
                float v = acc[i][j] + bi[i];
                bf16 h = __float2bfloat16_rn(v);
                hp[j] = h;
                lp[j] = __float2bfloat16_rn(v - __bfloat162float(h));
            }
            long off = (long)(o0 + i) * PN + pl0;
            *(uint4*)&H[off] = uh;
            *(uint4*)&L[off] = ul;
        }
    } else {
        bf16* T = ((y == 0) ? g_Qs : g_Ks) + (long)b * PN * 256;
#pragma unroll
        for (int j = 0; j < 8; j++) {
            uint4 uh, ul;
            bf16* hp = (bf16*)&uh; bf16* lp = (bf16*)&ul;
#pragma unroll
            for (int i = 0; i < 8; i++) {
                float v = acc[i][j] + bi[i];
                bf16 h = __float2bfloat16_rn(v);
                hp[i] = h;
                lp[i] = __float2bfloat16_rn(v - __bfloat162float(h));
            }
            long row = (long)(pl0 + j) * 256;
            *(uint4*)&T[row + o0] = uh;
            *(uint4*)&T[row + 128 + o0] = ul;
        }
    }
}

// ---------------- scores: S[b][q][p] = sum_c Kt[q][c]*Qt[p][c] ---------------
__global__ __launch_bounds__(256) void scores_mma_kernel() {
    int b = blockIdx.z;
    int p0 = blockIdx.x * 128;
    int q0 = blockIdx.y * 128;
    const bf16* Kt = g_Ks + ((long)b * PN + q0) * 256;
    const bf16* Qt = g_Qs + ((long)b * PN + p0) * 256;
    // passes: (Khi,Qhi), (Khi,Qlo), (Klo,Qhi)
    mma_gemm3(Kt, Qt, Kt, Qt + 128, Kt + 128, Qt,
              256, 256, 0, 128,
              g_S + (long)b * PN * PN + (long)q0 * PN + p0, PN);
}

// ---------------- softmax stats per (b,q) row --------------------------------
__global__ void stats_kernel() {
    long bq = blockIdx.x;
    const float4* r = (const float4*)(g_S + bq * PN);
    int t = threadIdx.x;
    float4 v = r[t];

    __shared__ float red[8];
    float m = fmaxf(fmaxf(v.x, v.y), fmaxf(v.z, v.w));
#pragma unroll
    for (int o = 16; o > 0; o >>= 1) m = fmaxf(m, __shfl_xor_sync(0xffffffffu, m, o));
    if ((t & 31) == 0) red[t >> 5] = m;
    __syncthreads();
    if (t < 32) {
        float x = (t < 8) ? red[t] : -INFINITY;
#pragma unroll
        for (int o = 4; o > 0; o >>= 1) x = fmaxf(x, __shfl_xor_sync(0xffffffffu, x, o));
        if (t == 0) red[0] = x;
    }
    __syncthreads();
    float bm = red[0];
    __syncthreads();

    float s = expf(v.x - bm) + expf(v.y - bm) + expf(v.z - bm) + expf(v.w - bm);
#pragma unroll
    for (int o = 16; o > 0; o >>= 1) s += __shfl_xor_sync(0xffffffffu, s, o);
    if ((t & 31) == 0) red[t >> 5] = s;
    __syncthreads();
    if (t < 32) {
        float x = (t < 8) ? red[t] : 0.f;
#pragma unroll
        for (int o = 4; o > 0; o >>= 1) x += __shfl_xor_sync(0xffffffffu, x, o);
        if (t == 0) {
            g_smax[bq] = bm;
            g_sinv[bq] = 1.0f / x;
        }
    }
}

// ---------------- transpose + normalize + bf16 split: att^T[p][q] ------------
__global__ __launch_bounds__(256) void trans_kernel() {
    __shared__ float T[64][65];
    __shared__ float sm[64], si[64];
    int b = blockIdx.z;
    int p0 = blockIdx.x * 64;
    int q0 = blockIdx.y * 64;
    int t = threadIdx.x;
    const float* S = g_S + (long)b * PN * PN;

    if (t < 64) {
        sm[t] = g_smax[b * PN + q0 + t];
        si[t] = g_sinv[b * PN + q0 + t];
    }
    __syncthreads();

#pragma unroll
    for (int u = 0; u < 4; u++) {
        int idx = t + u * 256;
        int r = idx >> 4;
        int c4 = (idx & 15) * 4;
        float4 v = *(const float4*)&S[(long)(q0 + r) * PN + p0 + c4];
        float m = sm[r], sc = si[r];
        T[c4 + 0][r] = expf(v.x - m) * sc;
        T[c4 + 1][r] = expf(v.y - m) * sc;
        T[c4 + 2][r] = expf(v.z - m) * sc;
        T[c4 + 3][r] = expf(v.w - m) * sc;
    }
    __syncthreads();

    bf16* H = g_aThi + (long)b * PN * PN;
    bf16* L = g_aTlo + (long)b * PN * PN;
#pragma unroll
    for (int u = 0; u < 2; u++) {
        int idx = t + u * 256;
        int rr = idx >> 3;
        int s8 = (idx & 7) * 8;
        uint4 uh, ul;
        bf16* hp = (bf16*)&uh; bf16* lp = (bf16*)&ul;
#pragma unroll
        for (int j = 0; j < 8; j++) {
            float a = T[rr][s8 + j];
            bf16 h = __float2bfloat16_rn(a);
            hp[j] = h;
            lp[j] = __float2bfloat16_rn(a - __bfloat162float(h));
        }
        long off = (long)(p0 + rr) * PN + q0 + s8;
        *(uint4*)&H[off] = uh;
        *(uint4*)&L[off] = ul;
    }
}

// ---------------- x3: X3[c][p] = sum_q V[c][q]*attT[p][q], split-K=4 ---------
__global__ __launch_bounds__(256) void x3_mma_kernel() {
    int b = blockIdx.z;
    int p0 = blockIdx.x * 128;
    int ks = blockIdx.y;
    const bf16* Vh = g_Vhi + (long)b * CH * PN;
    const bf16* Vl = g_Vlo + (long)b * CH * PN;
    const bf16* ah = g_aThi + ((long)b * PN + p0) * PN;
    const bf16* al = g_aTlo + ((long)b * PN + p0) * PN;
    // passes: (Vhi,ahi), (Vhi,alo), (Vlo,ahi)
    mma_gemm3(Vh, ah, Vh, al, Vl, ah,
              PN, PN, ks * 256, ks * 256 + 256,
              g_X3 + (long)ks * BATCH * CH * PN + (long)b * CH * PN + p0, PN);
}

// ---------------- inverse hilbert + combine split-K + sigmoid gate -----------
__global__ void sig_kernel(const int* __restrict__ rehil,
                           const float* __restrict__ Wpre,
                           const float* __restrict__ bpre) {
    int t = blockIdx.x * blockDim.x + threadIdx.x;
    int b = t >> 16;
    int pix = t & 65535;
    int d = rehil[pix];
    int p = d >> 6;
    int j = d & 63;
    const long qtr = (long)BATCH * CH * PN;
    long base = (long)b * CH * PN;
    long i0 = base + j * PN + p;
    long i1 = base + (64 + j) * PN + p;
    float r0 = g_X3[i0] + g_X3[qtr + i0] + g_X3[2 * qtr + i0] + g_X3[3 * qtr + i0];
    float r1 = g_X3[i1] + g_X3[qtr + i1] + g_X3[2 * qtr + i1] + g_X3[3 * qtr + i1];
    float att = Wpre[0] * r0 + Wpre[1] * r1 + bpre[0];
    g_sig[t] = 1.0f / (1.0f + expf(-att));
}

// ---------------- final elementwise out = sig * x -----------------------------
__global__ void final_kernel(const float* __restrict__ x, float* __restrict__ out) {
    long i = blockIdx.x * (long)blockDim.x + threadIdx.x;
    int pixw = (int)(i & 16383);
    long bc = i >> 14;
    int b = (int)(bc >> 7);
    float4 s = ((const float4*)g_sig)[(long)b * (N_PIX / 4) + pixw];
    float4 v = ((const float4*)x)[i];
    v.x *= s.x; v.y *= s.y; v.z *= s.z; v.w *= s.w;
    ((float4*)out)[i] = v;
}

// ---------------- launch -------------------------------------------------------
extern "C" void kernel_launch(void* const* d_in, const int* in_sizes, int n_in,
                              void* d_out, int out_size) {
    const float* x    = (const float*)d_in[0];
    const float* Wq   = (const float*)d_in[1];
    const float* bq   = (const float*)d_in[2];
    const float* Wk   = (const float*)d_in[3];
    const float* bk   = (const float*)d_in[4];
    const float* Wv   = (const float*)d_in[5];
    const float* bv   = (const float*)d_in[6];
    const float* Wpre = (const float*)d_in[7];
    const float* bpre = (const float*)d_in[8];
    const int*   hil  = (const int*)d_in[9];
    const int*   rehil= (const int*)d_in[10];
    float* out = (float*)d_out;

    const int DSMEM = 65536;   // 2 stages * (16KB A + 16KB B)
    cudaFuncSetAttribute(scores_mma_kernel, cudaFuncAttributeMaxDynamicSharedMemorySize, DSMEM);
    cudaFuncSetAttribute(x3_mma_kernel, cudaFuncAttributeMaxDynamicSharedMemorySize, DSMEM);

    // 1) mean/max over channels
    meanmax_kernel<<<(BATCH * (N_PIX / 4)) / 256, 256>>>(x);

    // 2) hilbert gather -> feat
    gather_kernel<<<(BATCH * N_PIX) / 256, 256>>>(hil);

    // 3) fused QKV with bf16-split epilogues (192 blocks)
    {
        dim3 grid(PN / 128, 3, BATCH);
        qkv_kernel<<<grid, 256>>>(Wq, Wk, Wv, bq, bk, bv);
    }

    // 4) scores via mma.sync (512 blocks)
    {
        dim3 grid(PN / 128, PN / 128, BATCH);
        scores_mma_kernel<<<grid, 256, DSMEM>>>();
    }

    // 5) softmax stats
    stats_kernel<<<BATCH * PN, 256>>>();

    // 6) normalize + transpose + bf16 split (2048 blocks)
    {
        dim3 grid(PN / 64, PN / 64, BATCH);
        trans_kernel<<<grid, 256>>>();
    }

    // 7) x3 via mma.sync, split-K=4 (256 blocks)
    {
        dim3 grid(PN / 128, 4, BATCH);
        x3_mma_kernel<<<grid, 256, DSMEM>>>();
    }

    // 8) inverse hilbert + split-K combine + sigmoid gate
    sig_kernel<<<(BATCH * N_PIX) / 256, 256>>>(rehil, Wpre, bpre);

    // 9) out = sigmoid(att) * x
    final_kernel<<<(BATCH * C_IN * (N_PIX / 4)) / 256, 256>>>(x, out);
}

// round 7
// speedup vs baseline: 1.6648x; 1.0197x over previous
#include <cuda_runtime.h>
#include <cuda_bf16.h>
#include <math.h>
#include <stdint.h>

#define BATCH 8
#define C_IN 128
#define N_PIX 65536
#define CH 128
#define PN 1024

typedef __nv_bfloat16 bf16;

// ---------------- scratch (static device globals; no allocation) ------------
__device__ float g_x1[BATCH * 2 * N_PIX];
__device__ float g_feat[BATCH * CH * PN];
__device__ bf16  g_Qs[BATCH * PN * 256];      // Q^T: [b][p][hi(128)|lo(128)]
__device__ bf16  g_Ks[BATCH * PN * 256];      // K^T: [b][q][hi(128)|lo(128)]
__device__ bf16  g_Vhi[BATCH * CH * PN];      // V hi: [b][c][q]
__device__ bf16  g_Vlo[BATCH * CH * PN];
__device__ float g_S[BATCH * PN * PN];        // scores [b][p][q]  32 MB
__device__ float g_pm[BATCH * 8 * PN];        // per-p-slab column max partials
__device__ float g_ps[BATCH * 8 * PN];        // per-p-slab column sumexp partials
__device__ float g_smax[BATCH * PN];          // per-q max
__device__ float g_sinv[BATCH * PN];          // per-q 1/sumexp
__device__ bf16  g_athi[BATCH * PN * PN];     // att [b][p][q] hi
__device__ bf16  g_atlo[BATCH * PN * PN];     // att [b][p][q] lo
__device__ float g_X3[4 * BATCH * CH * PN];   // split-K=4 partials
__device__ float g_sig[BATCH * N_PIX];

// ---------------- helpers -----------------------------------------------------
__device__ __forceinline__ uint32_t s2u(const void* p) {
    uint32_t a;
    asm("{ .reg .u64 t; cvta.to.shared.u64 t, %1; cvt.u32.u64 %0, t; }" : "=r"(a) : "l"(p));
    return a;
}
#define SW128(off) ((off) ^ (((off) >> 3) & 0x70))

__device__ __forceinline__ void cp16(uint32_t dst, const void* src) {
    asm volatile("cp.async.cg.shared.global [%0], [%1], 16;" :: "r"(dst), "l"(src));
}
#define LDMX4(r0, r1, r2, r3, addr)                                            \
    asm volatile("ldmatrix.sync.aligned.m8n8.x4.shared.b16 {%0,%1,%2,%3}, [%4];" \
                 : "=r"(r0), "=r"(r1), "=r"(r2), "=r"(r3) : "r"(addr))
#define MMA16816(d, a, b)                                                      \
    asm volatile("mma.sync.aligned.m16n8k16.row.col.f32.bf16.bf16.f32 "        \
                 "{%0,%1,%2,%3},{%4,%5,%6,%7},{%8,%9},{%0,%1,%2,%3};"          \
                 : "+f"((d)[0]), "+f"((d)[1]), "+f"((d)[2]), "+f"((d)[3])      \
                 : "r"((a)[0]), "r"((a)[1]), "r"((a)[2]), "r"((a)[3]),         \
                   "r"((b)[0]), "r"((b)[1]))

// ---------------- 128x128 bf16 hi/lo GEMM body via mma.sync ------------------
// D[m][n] = sum over 3 passes, sum_{k=kbeg}^{kend} A[m][k]*B[n][k], fp32 accum.
// If STATS: additionally emit per-column (n) online-softmax partials over the
// 128 m-rows of this CTA into pm[n], ps[n].
template <bool STATS>
__device__ __forceinline__ void mma_gemm3(
    const bf16* A0, const bf16* B0,
    const bf16* A1, const bf16* B1,
    const bf16* A2, const bf16* B2,
    long sA, long sB, int kbeg, int kend,
    float* C, int ldC, float* pm, float* ps)
{
    extern __shared__ char smem[];
    const uint32_t sb = s2u(smem);
    const int tid = threadIdx.x, lane = tid & 31, wid = tid >> 5;
    const int wm = wid & 3;                   // 4 warps along m (32 rows each)
    const int wn = wid >> 2;                  // 2 warps along n (64 cols each)

    const int nk = (kend - kbeg) >> 6;        // 64-wide k chunks per pass
    const int total = 3 * nk;

    float acc[2][8][4];
#pragma unroll
    for (int i = 0; i < 2; i++)
#pragma unroll
        for (int j = 0; j < 8; j++)
#pragma unroll
            for (int v = 0; v < 4; v++) acc[i][j][v] = 0.f;

    auto issue = [&](int chunk) {
        int pass = chunk / nk, kk = chunk - pass * nk;
        const bf16* A = (pass == 0) ? A0 : (pass == 1) ? A1 : A2;
        const bf16* B = (pass == 0) ? B0 : (pass == 1) ? B1 : B2;
        long k0 = kbeg + kk * 64;
        uint32_t aoff = (chunk & 1) * 16384u;
        uint32_t boff = 32768u + (chunk & 1) * 16384u;
#pragma unroll
        for (int u = 0; u < 4; u++) {
            int seg = tid + u * 256;          // 0..1023
            int r = seg >> 3, s = (seg & 7) * 16;
            cp16(sb + aoff + SW128(r * 128 + s), (const char*)(A + (long)r * sA + k0) + s);
        }
#pragma unroll
        for (int u = 0; u < 4; u++) {
            int seg = tid + u * 256;
            int r = seg >> 3, s = (seg & 7) * 16;
            cp16(sb + boff + SW128(r * 128 + s), (const char*)(B + (long)r * sB + k0) + s);
        }
        asm volatile("cp.async.commit_group;" ::: "memory");
    };

    issue(0);
    for (int c = 0; c < total; c++) {
        if (c + 1 < total) {
            issue(c + 1);
            asm volatile("cp.async.wait_group 1;" ::: "memory");
        } else {
            asm volatile("cp.async.wait_group 0;" ::: "memory");
        }
        __syncthreads();

        const uint32_t abase = sb + (c & 1) * 16384u;
        const uint32_t bbase = sb + 32768u + (c & 1) * 16384u;
#pragma unroll
        for (int ks = 0; ks < 4; ks++) {
            uint32_t a[2][4], bf[8][2];
#pragma unroll
            for (int mf = 0; mf < 2; mf++) {
                int r = wm * 32 + mf * 16 + (lane & 15);
                int kb = ks * 32 + ((lane >> 4) << 4);
                LDMX4(a[mf][0], a[mf][1], a[mf][2], a[mf][3],
                      abase + SW128(r * 128 + kb));
            }
#pragma unroll
            for (int ng = 0; ng < 4; ng++) {
                int r = wn * 64 + ng * 16 + (lane & 7) + ((lane >> 4) << 3);
                int kb = ks * 32 + (((lane >> 3) & 1) << 4);
                LDMX4(bf[ng * 2][0], bf[ng * 2][1], bf[ng * 2 + 1][0], bf[ng * 2 + 1][1],
                      bbase + SW128(r * 128 + kb));
            }
#pragma unroll
            for (int mf = 0; mf < 2; mf++)
#pragma unroll
                for (int nf = 0; nf < 8; nf++)
                    MMA16816(acc[mf][nf], a[mf], bf[nf]);
        }
        __syncthreads();
    }

    const int g = lane >> 2, t = lane & 3;

    if (STATS) {
        // per-column online softmax partials over this CTA's 128 rows.
        float* spm = (float*)smem;            // [4][128]
        float* sps = (float*)smem + 512;      // [4][128]
#pragma unroll
        for (int nf = 0; nf < 8; nf++) {
#pragma unroll
            for (int cc = 0; cc < 2; cc++) {
                float v0 = acc[0][nf][cc], v1 = acc[0][nf][cc + 2];
                float v2 = acc[1][nf][cc], v3 = acc[1][nf][cc + 2];
                float m = fmaxf(fmaxf(v0, v1), fmaxf(v2, v3));
                float s = __expf(v0 - m) + __expf(v1 - m) +
                          __expf(v2 - m) + __expf(v3 - m);
#pragma unroll
                for (int o = 4; o <= 16; o <<= 1) {
                    float mo = __shfl_xor_sync(0xffffffffu, m, o);
                    float so = __shfl_xor_sync(0xffffffffu, s, o);
                    float M = fmaxf(m, mo);
                    s = s * __expf(m - M) + so * __expf(mo - M);
                    m = M;
                }
                if (g == 0) {
                    int col = wn * 64 + (nf >> 1) * 16 + (nf & 1) * 8 + 2 * t + cc;
                    spm[wm * 128 + col] = m;
                    sps[wm * 128 + col] = s;
                }
            }
        }
        __syncthreads();
        if (tid < 128) {
            float m = spm[tid], s = sps[tid];
#pragma unroll
            for (int w = 1; w < 4; w++) {
                float mo = spm[w * 128 + tid], so = sps[w * 128 + tid];
                float M = fmaxf(m, mo);
                s = s * __expf(m - M) + so * __expf(mo - M);
                m = M;
            }
            pm[tid] = m;
            ps[tid] = s;
        }
    }

    // write fp32 accumulators to C
#pragma unroll
    for (int mf = 0; mf < 2; mf++) {
        int row = wm * 32 + mf * 16 + g;
#pragma unroll
        for (int nf = 0; nf < 8; nf++) {
            int col = wn * 64 + (nf >> 1) * 16 + (nf & 1) * 8 + 2 * t;
            *(float2*)&C[(long)row * ldC + col] =
                make_float2(acc[mf][nf][0], acc[mf][nf][1]);
            *(float2*)&C[(long)(row + 8) * ldC + col] =
                make_float2(acc[mf][nf][2], acc[mf][nf][3]);
        }
    }
}

// ---------------- kernel 1: mean & max over channels ------------------------
__global__ void meanmax_kernel(const float* __restrict__ x) {
    int t = blockIdx.x * blockDim.x + threadIdx.x;
    int b = t >> 14;
    int w = t & 16383;
    const float4* xp = (const float4*)x + (long)b * C_IN * (N_PIX / 4) + w;
    float4 s = make_float4(0.f, 0.f, 0.f, 0.f);
    float4 m = make_float4(-INFINITY, -INFINITY, -INFINITY, -INFINITY);
#pragma unroll 8
    for (int c = 0; c < C_IN; c++) {
        float4 v = __ldcs(xp + (long)c * (N_PIX / 4));
        s.x += v.x; s.y += v.y; s.z += v.z; s.w += v.w;
        m.x = fmaxf(m.x, v.x); m.y = fmaxf(m.y, v.y);
        m.z = fmaxf(m.z, v.z); m.w = fmaxf(m.w, v.w);
    }
    const float inv = 1.0f / 128.0f;
    s.x *= inv; s.y *= inv; s.z *= inv; s.w *= inv;
    float4* o = (float4*)g_x1;
    o[(long)b * 2 * (N_PIX / 4) + w] = s;
    o[(long)b * 2 * (N_PIX / 4) + (N_PIX / 4) + w] = m;
}

// ---------------- kernel 2: hilbert gather + pool transpose -----------------
__global__ void gather_kernel(const int* __restrict__ hil) {
    int t = blockIdx.x * blockDim.x + threadIdx.x;
    int b = t >> 16;
    int d = t & 65535;
    int pix = hil[d];
    int p = d >> 6;
    int j = d & 63;
    float mean = g_x1[(long)b * 2 * N_PIX + pix];
    float mx   = g_x1[(long)b * 2 * N_PIX + N_PIX + pix];
    g_feat[(long)b * CH * PN + j * PN + p]        = mean;
    g_feat[(long)b * CH * PN + (64 + j) * PN + p] = mx;
}

// ---------------- QKV SIMT GEMM with bf16-split epilogues -------------------
__global__ __launch_bounds__(256) void qkv_kernel(
    const float* __restrict__ Wq, const float* __restrict__ Wk, const float* __restrict__ Wv,
    const float* __restrict__ bq, const float* __restrict__ bk, const float* __restrict__ bv)
{
    __shared__ float As[16][132];
    __shared__ float Bs[16][128];

    int b = blockIdx.z;
    int p0 = blockIdx.x * 128;
    int y = blockIdx.y;
    const float* W    = (y == 0) ? Wq : (y == 1) ? Wk : Wv;
    const float* bias = (y == 0) ? bq : (y == 1) ? bk : bv;
    const float* B = g_feat + (long)b * CH * PN;

    int tid = threadIdx.x;
    int tx = tid & 15;
    int ty = tid >> 4;

    float acc[8][8];
#pragma unroll
    for (int i = 0; i < 8; i++)
#pragma unroll
        for (int j = 0; j < 8; j++) acc[i][j] = 0.f;

    for (int k0 = 0; k0 < CH; k0 += 16) {
#pragma unroll
        for (int u = 0; u < 2; u++) {
            int idx = tid + u * 256;
            int m = idx >> 2, kq = (idx & 3) * 4;
            float4 v = *(const float4*)&W[(long)m * CH + k0 + kq];
            As[kq + 0][m] = v.x; As[kq + 1][m] = v.y;
            As[kq + 2][m] = v.z; As[kq + 3][m] = v.w;
        }
#pragma unroll
        for (int u = 0; u < 2; u++) {
            int idx = tid + u * 256;
            int k = idx >> 5, n4 = (idx & 31) * 4;
            *(float4*)&Bs[k][n4] = *(const float4*)&B[(long)(k0 + k) * PN + p0 + n4];
        }
        __syncthreads();
#pragma unroll
        for (int k = 0; k < 16; k++) {
            float a[8], bb[8];
#pragma unroll
            for (int i = 0; i < 8; i++) a[i] = As[k][ty * 8 + i];
#pragma unroll
            for (int j = 0; j < 8; j++) bb[j] = Bs[k][tx * 8 + j];
#pragma unroll
            for (int i = 0; i < 8; i++)
#pragma unroll
                for (int j = 0; j < 8; j++) acc[i][j] += a[i] * bb[j];
        }
        __syncthreads();
    }

    int o0 = ty * 8;
    int pl0 = p0 + tx * 8;
    float bi[8];
#pragma unroll
    for (int i = 0; i < 8; i++) bi[i] = bias[o0 + i];

    if (y == 2) {
        bf16* H = g_Vhi + (long)b * CH * PN;
        bf16* L = g_Vlo + (long)b * CH * PN;
#pragma unroll
        for (int i = 0; i < 8; i++) {
            uint4 uh, ul;
            bf16* hp = (bf16*)&uh; bf16* lp = (bf16*)&ul;
#pragma unroll
            for (int j = 0; j < 8; j++) {
                float v = acc[i][j] + bi[i];
                bf16 h = __float2bfloat16_rn(v);
                hp[j] = h;
                lp[j] = __float2bfloat16_rn(v - __bfloat162float(h));
            }
            long off = (long)(o0 + i) * PN + pl0;
            *(uint4*)&H[off] = uh;
            *(uint4*)&L[off] = ul;
        }
    } else {
        bf16* T = ((y == 0) ? g_Qs : g_Ks) + (long)b * PN * 256;
#pragma unroll
        for (int j = 0; j < 8; j++) {
            uint4 uh, ul;
            bf16* hp = (bf16*)&uh; bf16* lp = (bf16*)&ul;
#pragma unroll
            for (int i = 0; i < 8; i++) {
                float v = acc[i][j] + bi[i];
                bf16 h = __float2bfloat16_rn(v);
                hp[i] = h;
                lp[i] = __float2bfloat16_rn(v - __bfloat162float(h));
            }
            long row = (long)(pl0 + j) * 256;
            *(uint4*)&T[row + o0] = uh;
            *(uint4*)&T[row + 128 + o0] = ul;
        }
    }
}

// ---------------- scores: S[b][p][q] = sum_c Qt[p][c]*Kt[q][c] + col stats ---
__global__ __launch_bounds__(256, 2) void scores_mma_kernel() {
    int b = blockIdx.z;
    int q0 = blockIdx.x * 128;
    int p0 = blockIdx.y * 128;
    const bf16* Qt = g_Qs + ((long)b * PN + p0) * 256;
    const bf16* Kt = g_Ks + ((long)b * PN + q0) * 256;
    float* pm = g_pm + ((b * 8 + (p0 >> 7)) << 10) + q0;
    float* ps = g_ps + ((b * 8 + (p0 >> 7)) << 10) + q0;
    // passes: (Qhi,Khi), (Qhi,Klo), (Qlo,Khi)
    mma_gemm3<true>(Qt, Kt, Qt, Kt + 128, Qt + 128, Kt,
                    256, 256, 0, 128,
                    g_S + (long)b * PN * PN + (long)p0 * PN + q0, PN, pm, ps);
}

// ---------------- combine 8 p-slab partials -> m[q], 1/sum[q] ---------------
__global__ void statcombine_kernel() {
    int i = blockIdx.x * 256 + threadIdx.x;   // 8192 = BATCH*PN
    int b = i >> 10, q = i & 1023;
    float m = -INFINITY, s = 0.f;
#pragma unroll
    for (int sl = 0; sl < 8; sl++) {
        float mo = g_pm[((b * 8 + sl) << 10) + q];
        float so = g_ps[((b * 8 + sl) << 10) + q];
        float M = fmaxf(m, mo);
        s = s * __expf(m - M) + so * __expf(mo - M);
        m = M;
    }
    g_smax[i] = m;
    g_sinv[i] = 1.0f / s;
}

// ---------------- elementwise exp-normalize + bf16 hi/lo split ---------------
__global__ void expnorm_kernel() {
    long i = blockIdx.x * 256L + threadIdx.x;     // BATCH*PN*PN/4 float4s
    int q4 = (int)(i & 255);
    int b = (int)(i >> 18);
    float4 sv = ((const float4*)g_S)[i];
    float4 mv = ((const float4*)g_smax)[b * 256 + q4];
    float4 iv = ((const float4*)g_sinv)[b * 256 + q4];
    float e0 = expf(sv.x - mv.x) * iv.x;
    float e1 = expf(sv.y - mv.y) * iv.y;
    float e2 = expf(sv.z - mv.z) * iv.z;
    float e3 = expf(sv.w - mv.w) * iv.w;
    uint2 uh, ul;
    bf16* hp = (bf16*)&uh; bf16* lp = (bf16*)&ul;
    bf16 h;
    h = __float2bfloat16_rn(e0); hp[0] = h; lp[0] = __float2bfloat16_rn(e0 - __bfloat162float(h));
    h = __float2bfloat16_rn(e1); hp[1] = h; lp[1] = __float2bfloat16_rn(e1 - __bfloat162float(h));
    h = __float2bfloat16_rn(e2); hp[2] = h; lp[2] = __float2bfloat16_rn(e2 - __bfloat162float(h));
    h = __float2bfloat16_rn(e3); hp[3] = h; lp[3] = __float2bfloat16_rn(e3 - __bfloat162float(h));
    ((uint2*)g_athi)[i] = uh;
    ((uint2*)g_atlo)[i] = ul;
}

// ---------------- x3: X3[c][p] = sum_q V[c][q]*att[p][q], split-K=4 ----------
__global__ __launch_bounds__(256, 2) void x3_mma_kernel() {
    int b = blockIdx.z;
    int p0 = blockIdx.x * 128;
    int ks = blockIdx.y;
    const bf16* Vh = g_Vhi + (long)b * CH * PN;
    const bf16* Vl = g_Vlo + (long)b * CH * PN;
    const bf16* ah = g_athi + ((long)b * PN + p0) * PN;
    const bf16* al = g_atlo + ((long)b * PN + p0) * PN;
    // passes: (Vhi,athi), (Vhi,atlo), (Vlo,athi)
    mma_gemm3<false>(Vh, ah, Vh, al, Vl, ah,
                     PN, PN, ks * 256, ks * 256 + 256,
                     g_X3 + (long)ks * BATCH * CH * PN + (long)b * CH * PN + p0, PN,
                     nullptr, nullptr);
}

// ---------------- inverse hilbert + combine split-K + sigmoid gate -----------
__global__ void sig_kernel(const int* __restrict__ rehil,
                           const float* __restrict__ Wpre,
                           const float* __restrict__ bpre) {
    int t = blockIdx.x * blockDim.x + threadIdx.x;
    int b = t >> 16;
    int pix = t & 65535;
    int d = rehil[pix];
    int p = d >> 6;
    int j = d & 63;
    const long qtr = (long)BATCH * CH * PN;
    long base = (long)b * CH * PN;
    long i0 = base + j * PN + p;
    long i1 = base + (64 + j) * PN + p;
    float r0 = g_X3[i0] + g_X3[qtr + i0] + g_X3[2 * qtr + i0] + g_X3[3 * qtr + i0];
    float r1 = g_X3[i1] + g_X3[qtr + i1] + g_X3[2 * qtr + i1] + g_X3[3 * qtr + i1];
    float att = Wpre[0] * r0 + Wpre[1] * r1 + bpre[0];
    g_sig[t] = 1.0f / (1.0f + expf(-att));
}

// ---------------- final elementwise out = sig * x -----------------------------
__global__ void final_kernel(const float* __restrict__ x, float* __restrict__ out) {
    long i = blockIdx.x * (long)blockDim.x + threadIdx.x;
    int pixw = (int)(i & 16383);
    long bc = i >> 14;
    int b = (int)(bc >> 7);
    float4 s = ((const float4*)g_sig)[(long)b * (N_PIX / 4) + pixw];
    float4 v = __ldcs((const float4*)x + i);
    v.x *= s.x; v.y *= s.y; v.z *= s.z; v.w *= s.w;
    __stcs((float4*)out + i, v);
}

// ---------------- launch -------------------------------------------------------
extern "C" void kernel_launch(void* const* d_in, const int* in_sizes, int n_in,
                              void* d_out, int out_size) {
    const float* x    = (const float*)d_in[0];
    const float* Wq   = (const float*)d_in[1];
    const float* bq   = (const float*)d_in[2];
    const float* Wk   = (const float*)d_in[3];
    const float* bk   = (const float*)d_in[4];
    const float* Wv   = (const float*)d_in[5];
    const float* bv   = (const float*)d_in[6];
    const float* Wpre = (const float*)d_in[7];
    const float* bpre = (const float*)d_in[8];
    const int*   hil  = (const int*)d_in[9];
    const int*   rehil= (const int*)d_in[10];
    float* out = (float*)d_out;

    const int DSMEM = 65536;   // 2 stages * (16KB A + 16KB B); stats reuse
    cudaFuncSetAttribute(scores_mma_kernel, cudaFuncAttributeMaxDynamicSharedMemorySize, DSMEM);
    cudaFuncSetAttribute(x3_mma_kernel, cudaFuncAttributeMaxDynamicSharedMemorySize, DSMEM);

    // 1) mean/max over channels
    meanmax_kernel<<<(BATCH * (N_PIX / 4)) / 256, 256>>>(x);

    // 2) hilbert gather -> feat
    gather_kernel<<<(BATCH * N_PIX) / 256, 256>>>(hil);

    // 3) fused QKV with bf16-split epilogues (192 blocks)
    {
        dim3 grid(PN / 128, 3, BATCH);
        qkv_kernel<<<grid, 256>>>(Wq, Wk, Wv, bq, bk, bv);
    }

    // 4) scores via mma.sync, S[p][q] + fused column-softmax partials (512 blocks)
    {
        dim3 grid(PN / 128, PN / 128, BATCH);
        scores_mma_kernel<<<grid, 256, DSMEM>>>();
    }

    // 5) combine slab partials -> m[q], 1/sum[q]   (32 blocks, tiny)
    statcombine_kernel<<<BATCH * PN / 256, 256>>>();

    // 6) elementwise exp-normalize + hi/lo split (8192 blocks)
    expnorm_kernel<<<(int)((long)BATCH * PN * PN / 4 / 256), 256>>>();

    // 7) x3 via mma.sync, split-K=4 (256 blocks)
    {
        dim3 grid(PN / 128, 4, BATCH);
        x3_mma_kernel<<<grid, 256, DSMEM>>>();
    }

    // 8) inverse hilbert + split-K combine + sigmoid gate
    sig_kernel<<<(BATCH * N_PIX) / 256, 256>>>(rehil, Wpre, bpre);

    // 9) out = sigmoid(att) * x
    final_kernel<<<(BATCH * C_IN * (N_PIX / 4)) / 256, 256>>>(x, out);
}